// round 10
// baseline (speedup 1.0000x reference)
#include <cuda_runtime.h>
#include <cuda_fp16.h>
#include <math.h>

#define N_NODES 8192
#define NFEAT   256
#define NHID    64
#define NHEADS  4
#define DHID    (NHEADS*NHID)   /* 256 */
#define NCLASS  121
#define LDC2    128             /* padded ld for Whc (halfs) */
#define MAXDEG  512
#define LRELU_ALPHA 0.2f

/* ---------------- scratch (static device globals; no allocs) -------------- */
__device__ __half g_Wh_h[N_NODES * DHID];     /* 4 MB layer-1 Wh (fp16, gather-only) */
__device__ float  g_fs[NHEADS * N_NODES];
__device__ float  g_fd[NHEADS * N_NODES];
__device__ float  g_hcat[N_NODES * DHID];     /* 8 MB layer-1 output (fp32, GEMM2 A) */
__device__ __half g_Whc_h[N_NODES * LDC2];    /* 2 MB layer-2 Wh (fp16, gather-only) */
__device__ float  g_v2s[DHID];
__device__ float  g_v2d[DHID];
__device__ float  g_f2s[N_NODES];
__device__ float  g_f2d[N_NODES];
__device__ int    g_cols[(size_t)N_NODES * MAXDEG];  /* 16 MB edge lists */
__device__ int    g_deg[N_NODES];

/* ---------------- 1. build per-row edge lists (one pass over adj) --------- */
__global__ void build_edges(const float* __restrict__ adj) {
    int row = blockIdx.x;
    int tid = threadIdx.x;
    const float4* a4 = (const float4*)(adj + (size_t)row * N_NODES + tid * 32);

    float4 v[8];
    int cnt = 0;
#pragma unroll
    for (int q = 0; q < 8; q++) {
        v[q] = a4[q];
        cnt += (v[q].x > 0.f) + (v[q].y > 0.f) + (v[q].z > 0.f) + (v[q].w > 0.f);
    }

    __shared__ int s[256];
    s[tid] = cnt;
    __syncthreads();
    for (int off = 1; off < 256; off <<= 1) {
        int t = (tid >= off) ? s[tid - off] : 0;
        __syncthreads();
        s[tid] += t;
        __syncthreads();
    }
    int pos = s[tid] - cnt;            /* exclusive prefix */
    if (tid == 0) {
        int total = s[255];
        g_deg[row] = total < MAXDEG ? total : MAXDEG;
    }

    int* outc = g_cols + (size_t)row * MAXDEG;
#pragma unroll
    for (int q = 0; q < 8; q++) {
        int base = tid * 32 + q * 4;
        if (v[q].x > 0.f) { if (pos < MAXDEG) outc[pos] = base + 0; pos++; }
        if (v[q].y > 0.f) { if (pos < MAXDEG) outc[pos] = base + 1; pos++; }
        if (v[q].z > 0.f) { if (pos < MAXDEG) outc[pos] = base + 2; pos++; }
        if (v[q].w > 0.f) { if (pos < MAXDEG) outc[pos] = base + 3; pos++; }
    }
}

/* ---------------- 2b. v2 = W_out @ a_out halves (warp per row) ------------ */
__global__ void prep_v2(const float* __restrict__ W_out, const float* __restrict__ a_out) {
    int warp = (blockIdx.x << 3) + (threadIdx.x >> 5);   /* 32 blocks * 8 warps = 256 */
    int lane = threadIdx.x & 31;
    const float* wrow = W_out + (size_t)warp * NCLASS;
    float s = 0.f, d = 0.f;
    for (int c = lane; c < NCLASS; c += 32) {
        float w = wrow[c];
        s += w * a_out[c];
        d += w * a_out[NCLASS + c];
    }
#pragma unroll
    for (int o = 16; o > 0; o >>= 1) {
        s += __shfl_xor_sync(0xffffffffu, s, o);
        d += __shfl_xor_sync(0xffffffffu, d, o);
    }
    if (lane == 0) { g_v2s[warp] = s; g_v2d[warp] = d; }
}

/* ---------------- 3. SGEMM1: Wh = x @ Ws[h], fused f-scores, fp16 out ----- */
/* BM=64, BN=64 (=one head, B read directly from Ws), BK=16, 256 thr, 4x4.  */
__global__ void sgemm1(const float* __restrict__ A, const float* __restrict__ Ws,
                       const float* __restrict__ a_heads) {
    __shared__ float As[16][64];
    __shared__ float Bs[16][64];
    __shared__ float s_as[64], s_ad[64];
    int tid = threadIdx.x;
    int tx = tid & 15, ty = tid >> 4;
    int h = blockIdx.x;                 /* head = column tile */
    int row0 = blockIdx.y * 64;
    const int K = NFEAT;
    const float* B = Ws + (size_t)h * NFEAT * NHID;   /* [256,64] contiguous */

    if (tid < 64)       s_as[tid]      = a_heads[h * 128 + tid];
    else if (tid < 128) s_ad[tid - 64] = a_heads[h * 128 + tid];

    float acc[4][4];
#pragma unroll
    for (int i = 0; i < 4; i++)
#pragma unroll
        for (int j = 0; j < 4; j++) acc[i][j] = 0.f;

    int ar = tid & 63,  ac = (tid >> 6) * 4;   /* 64x16 tile, 1 float4/thread */
    int br = tid >> 4;
    int bc = (tid & 15) * 4;

    float4 a_reg = *(const float4*)(A + (size_t)(row0 + ar) * K + ac);
    float4 b_reg = *(const float4*)(B + (size_t)br * NHID + bc);
    __syncthreads();   /* covers s_as/s_ad */

    for (int k0 = 0; k0 < K; k0 += 16) {
        As[ac + 0][ar] = a_reg.x; As[ac + 1][ar] = a_reg.y;
        As[ac + 2][ar] = a_reg.z; As[ac + 3][ar] = a_reg.w;
        *(float4*)&Bs[br][bc] = b_reg;
        __syncthreads();

        if (k0 + 16 < K) {
            a_reg = *(const float4*)(A + (size_t)(row0 + ar) * K + (k0 + 16) + ac);
            b_reg = *(const float4*)(B + (size_t)(k0 + 16 + br) * NHID + bc);
        }

#pragma unroll
        for (int kk = 0; kk < 16; kk++) {
            float4 ra = *(const float4*)&As[kk][ty * 4];
            float4 rb = *(const float4*)&Bs[kk][tx * 4];
            float rav[4] = {ra.x, ra.y, ra.z, ra.w};
#pragma unroll
            for (int i = 0; i < 4; i++) {
                acc[i][0] += rav[i] * rb.x;
                acc[i][1] += rav[i] * rb.y;
                acc[i][2] += rav[i] * rb.z;
                acc[i][3] += rav[i] * rb.w;
            }
        }
        __syncthreads();
    }

    /* store C (fp16) + fused per-head f-scores (reduce across tx=16 lanes) */
#pragma unroll
    for (int i = 0; i < 4; i++) {
        int r = row0 + ty * 4 + i;
        __half2* dst = (__half2*)(g_Wh_h + (size_t)r * DHID + h * 64 + tx * 4);
        dst[0] = __floats2half2_rn(acc[i][0], acc[i][1]);
        dst[1] = __floats2half2_rn(acc[i][2], acc[i][3]);
        float ps = 0.f, pd = 0.f;
#pragma unroll
        for (int j = 0; j < 4; j++) {
            int c = tx * 4 + j;
            ps += acc[i][j] * s_as[c];
            pd += acc[i][j] * s_ad[c];
        }
#pragma unroll
        for (int o = 8; o > 0; o >>= 1) {
            ps += __shfl_xor_sync(0xffffffffu, ps, o);
            pd += __shfl_xor_sync(0xffffffffu, pd, o);
        }
        if (tx == 0) {
            g_fs[h * N_NODES + r] = ps;
            g_fd[h * N_NODES + r] = pd;
        }
    }
}

/* ---------------- 3b. SGEMM2: Whc = hcat @ W_out -> fp16 (ld 128) --------- */
/* BM=64, BN=64, BK=16, 256 thr, 4x4 reg tile.                              */
__global__ void sgemm2(const float* __restrict__ A, const float* __restrict__ B) {
    __shared__ float As[16][64];
    __shared__ float Bs[16][64];
    int tid = threadIdx.x;
    int tx = tid & 15, ty = tid >> 4;
    int row0 = blockIdx.y * 64;
    int col0 = blockIdx.x * 64;
    const int K = DHID, N = NCLASS;

    float acc[4][4];
#pragma unroll
    for (int i = 0; i < 4; i++)
#pragma unroll
        for (int j = 0; j < 4; j++) acc[i][j] = 0.f;

    int ar = tid & 63,  ac = (tid >> 6) * 4;
    int br = tid >> 4;
    int bc = (tid & 15) * 4;

    float4 a_reg = *(const float4*)(A + (size_t)(row0 + ar) * K + ac);
    float  b_reg[4];
#pragma unroll
    for (int j = 0; j < 4; j++) {
        int c = col0 + bc + j;
        b_reg[j] = (c < N) ? B[(size_t)br * N + c] : 0.f;
    }

    for (int k0 = 0; k0 < K; k0 += 16) {
        As[ac + 0][ar] = a_reg.x; As[ac + 1][ar] = a_reg.y;
        As[ac + 2][ar] = a_reg.z; As[ac + 3][ar] = a_reg.w;
#pragma unroll
        for (int j = 0; j < 4; j++) Bs[br][bc + j] = b_reg[j];
        __syncthreads();

        if (k0 + 16 < K) {
            a_reg = *(const float4*)(A + (size_t)(row0 + ar) * K + (k0 + 16) + ac);
#pragma unroll
            for (int j = 0; j < 4; j++) {
                int c = col0 + bc + j;
                b_reg[j] = (c < N) ? B[(size_t)(k0 + 16 + br) * N + c] : 0.f;
            }
        }

#pragma unroll
        for (int kk = 0; kk < 16; kk++) {
            float4 ra = *(const float4*)&As[kk][ty * 4];
            float4 rb = *(const float4*)&Bs[kk][tx * 4];
            float rav[4] = {ra.x, ra.y, ra.z, ra.w};
#pragma unroll
            for (int i = 0; i < 4; i++) {
                acc[i][0] += rav[i] * rb.x;
                acc[i][1] += rav[i] * rb.y;
                acc[i][2] += rav[i] * rb.z;
                acc[i][3] += rav[i] * rb.w;
            }
        }
        __syncthreads();
    }
#pragma unroll
    for (int i = 0; i < 4; i++) {
        int r = row0 + ty * 4 + i;
#pragma unroll
        for (int j = 0; j < 4; j++) {
            int c = col0 + tx * 4 + j;
            if (c < LDC2)
                g_Whc_h[(size_t)r * LDC2 + c] = __float2half_rn(c < N ? acc[i][j] : 0.f);
        }
    }
}

/* ---------------- 5. layer-1 softmax-aggregate + ELU + fused f2 ----------- */
/* 256 threads. Softmax: 4 heads x 64 lanes. Gather: 64 feat-lanes x 4       */
/* features (8B load) x 4 edge-chunks.                                       */
__global__ void agg1() {
    int row = blockIdx.x, tid = threadIdx.x;
    int h = tid >> 6, f = tid & 63;
    __shared__ int    s_col[MAXDEG];
    __shared__ float  s_w[NHEADS][MAXDEG];
    __shared__ float  s_rmax[8], s_rsum[8];
    __shared__ float  s_m[NHEADS], s_d[NHEADS];
    __shared__ float4 s_red[3][64];
    __shared__ float  s_ps[2], s_pd[2];

    int deg = g_deg[row];
    for (int k = tid; k < deg; k += 256)
        s_col[k] = g_cols[(size_t)row * MAXDEG + k];
    __syncthreads();

    float fsi = g_fs[h * N_NODES + row];
    const float* fdh = g_fd + h * N_NODES;

    float m = -1e30f;
    for (int k = f; k < deg; k += 64) {
        float e = fsi + __ldg(fdh + s_col[k]);
        e = (e > 0.f) ? e : LRELU_ALPHA * e;
        s_w[h][k] = e;
        m = fmaxf(m, e);
    }
#pragma unroll
    for (int o = 16; o > 0; o >>= 1) m = fmaxf(m, __shfl_xor_sync(0xffffffffu, m, o));
    int w = tid >> 5;
    if ((tid & 31) == 0) s_rmax[w] = m;
    __syncthreads();
    if (f == 0) s_m[h] = fmaxf(s_rmax[2 * h], s_rmax[2 * h + 1]);
    __syncthreads();
    float mh = s_m[h];

    float lsum = 0.f;
    for (int k = f; k < deg; k += 64) {
        float wv = expf(s_w[h][k] - mh);
        s_w[h][k] = wv;
        lsum += wv;
    }
#pragma unroll
    for (int o = 16; o > 0; o >>= 1) lsum += __shfl_xor_sync(0xffffffffu, lsum, o);
    if ((tid & 31) == 0) s_rsum[w] = lsum;
    __syncthreads();
    if (f == 0) s_d[h] = s_rsum[2 * h] + s_rsum[2 * h + 1];
    __syncthreads();

    /* gather: lane = 4 features, 4 edge-chunks */
    int lane = tid & 63;
    int chunk = tid >> 6;             /* 0..3 */
    int f4 = lane * 4;                /* feature base */
    int hh = f4 >> 6;
    const float* wrow = s_w[hh];
    float a0 = 0.f, a1 = 0.f, a2 = 0.f, a3 = 0.f;
    for (int k = chunk; k < deg; k += 4) {
        float wv = wrow[k];
        uint2 u = *(const uint2*)(g_Wh_h + (size_t)s_col[k] * DHID + f4);
        float2 p0 = __half22float2(*(__half2*)&u.x);
        float2 p1 = __half22float2(*(__half2*)&u.y);
        a0 += wv * p0.x; a1 += wv * p0.y;
        a2 += wv * p1.x; a3 += wv * p1.y;
    }
    if (chunk > 0) s_red[chunk - 1][lane] = make_float4(a0, a1, a2, a3);
    __syncthreads();
    if (chunk == 0) {
#pragma unroll
        for (int c = 0; c < 3; c++) {
            float4 t = s_red[c][lane];
            a0 += t.x; a1 += t.y; a2 += t.z; a3 += t.w;
        }
        float inv = 1.f / s_d[hh];
        a0 *= inv; a1 *= inv; a2 *= inv; a3 *= inv;
        a0 = (a0 > 0.f) ? a0 : expm1f(a0);
        a1 = (a1 > 0.f) ? a1 : expm1f(a1);
        a2 = (a2 > 0.f) ? a2 : expm1f(a2);
        a3 = (a3 > 0.f) ? a3 : expm1f(a3);
        *(float4*)(g_hcat + (size_t)row * DHID + f4) = make_float4(a0, a1, a2, a3);
        /* fused layer-2 f-scores */
        float ps = a0 * g_v2s[f4] + a1 * g_v2s[f4 + 1] + a2 * g_v2s[f4 + 2] + a3 * g_v2s[f4 + 3];
        float pd = a0 * g_v2d[f4] + a1 * g_v2d[f4 + 1] + a2 * g_v2d[f4 + 2] + a3 * g_v2d[f4 + 3];
#pragma unroll
        for (int o = 16; o > 0; o >>= 1) {
            ps += __shfl_xor_sync(0xffffffffu, ps, o);
            pd += __shfl_xor_sync(0xffffffffu, pd, o);
        }
        if ((tid & 31) == 0) { s_ps[tid >> 5] = ps; s_pd[tid >> 5] = pd; }
    }
    __syncthreads();
    if (tid == 0) {
        g_f2s[row] = s_ps[0] + s_ps[1];
        g_f2d[row] = s_pd[0] + s_pd[1];
    }
}

/* ---------------- 7. layer-2 softmax-aggregate (no ELU) ------------------- */
/* 128 threads. Gather: 32 feat-lanes x 4 features (8B) x 4 edge-chunks.     */
__global__ void agg2(float* __restrict__ out) {
    int row = blockIdx.x, tid = threadIdx.x;
    __shared__ int    s_col[MAXDEG];
    __shared__ float  s_w[MAXDEG];
    __shared__ float  s_rmax[4], s_rsum[4];
    __shared__ float  s_m, s_den;
    __shared__ float4 s_red[3][32];

    int deg = g_deg[row];
    for (int k = tid; k < deg; k += 128)
        s_col[k] = g_cols[(size_t)row * MAXDEG + k];
    __syncthreads();

    float fsi = g_f2s[row];
    float m = -1e30f;
    for (int k = tid; k < deg; k += 128) {
        float e = fsi + __ldg(g_f2d + s_col[k]);
        e = (e > 0.f) ? e : LRELU_ALPHA * e;
        s_w[k] = e;
        m = fmaxf(m, e);
    }
#pragma unroll
    for (int o = 16; o > 0; o >>= 1) m = fmaxf(m, __shfl_xor_sync(0xffffffffu, m, o));
    int w = tid >> 5;
    if ((tid & 31) == 0) s_rmax[w] = m;
    __syncthreads();
    if (tid == 0) s_m = fmaxf(fmaxf(s_rmax[0], s_rmax[1]), fmaxf(s_rmax[2], s_rmax[3]));
    __syncthreads();
    float mh = s_m;

    float lsum = 0.f;
    for (int k = tid; k < deg; k += 128) {
        float wv = expf(s_w[k] - mh);
        s_w[k] = wv;
        lsum += wv;
    }
#pragma unroll
    for (int o = 16; o > 0; o >>= 1) lsum += __shfl_xor_sync(0xffffffffu, lsum, o);
    if ((tid & 31) == 0) s_rsum[w] = lsum;
    __syncthreads();
    if (tid == 0) s_den = s_rsum[0] + s_rsum[1] + s_rsum[2] + s_rsum[3];
    __syncthreads();
    float inv = 1.f / s_den;

    int lane = tid & 31;
    int chunk = tid >> 5;             /* 0..3 */
    int f4 = lane * 4;                /* 0..124 */
    float a0 = 0.f, a1 = 0.f, a2 = 0.f, a3 = 0.f;
    for (int k = chunk; k < deg; k += 4) {
        float wv = s_w[k];
        uint2 u = *(const uint2*)(g_Whc_h + (size_t)s_col[k] * LDC2 + f4);
        float2 p0 = __half22float2(*(__half2*)&u.x);
        float2 p1 = __half22float2(*(__half2*)&u.y);
        a0 += wv * p0.x; a1 += wv * p0.y;
        a2 += wv * p1.x; a3 += wv * p1.y;
    }
    if (chunk > 0) s_red[chunk - 1][lane] = make_float4(a0, a1, a2, a3);
    __syncthreads();
    if (chunk == 0) {
#pragma unroll
        for (int c = 0; c < 3; c++) {
            float4 t = s_red[c][lane];
            a0 += t.x; a1 += t.y; a2 += t.z; a3 += t.w;
        }
        a0 *= inv; a1 *= inv; a2 *= inv; a3 *= inv;
        float* orow = out + (size_t)row * NCLASS;
        if (f4     < NCLASS) orow[f4]     = a0;
        if (f4 + 1 < NCLASS) orow[f4 + 1] = a1;
        if (f4 + 2 < NCLASS) orow[f4 + 2] = a2;
        if (f4 + 3 < NCLASS) orow[f4 + 3] = a3;
    }
}

/* ---------------- launch ------------------------------------------------- */
extern "C" void kernel_launch(void* const* d_in, const int* in_sizes, int n_in,
                              void* d_out, int out_size) {
    const float* x       = (const float*)d_in[0];   /* [8192,256]  */
    const float* adj     = (const float*)d_in[1];   /* [8192,8192] */
    const float* Ws      = (const float*)d_in[2];   /* [4,256,64]  */
    const float* a_heads = (const float*)d_in[3];   /* [4,128]     */
    const float* W_out   = (const float*)d_in[4];   /* [256,121]   */
    const float* a_out   = (const float*)d_in[5];   /* [242]       */
    float* out = (float*)d_out;                     /* [8192,121]  */

    /* side streams + events created once (host resources only) */
    static cudaStream_t s_side = 0, s_side2 = 0;
    static cudaEvent_t  ev_fork = 0, ev_join = 0, ev_join2 = 0;
    if (s_side == 0) {
        cudaStreamCreateWithFlags(&s_side,  cudaStreamNonBlocking);
        cudaStreamCreateWithFlags(&s_side2, cudaStreamNonBlocking);
        cudaEventCreateWithFlags(&ev_fork,  cudaEventDisableTiming);
        cudaEventCreateWithFlags(&ev_join,  cudaEventDisableTiming);
        cudaEventCreateWithFlags(&ev_join2, cudaEventDisableTiming);
    }

    float* p_hcat; cudaGetSymbolAddress((void**)&p_hcat, g_hcat);

    /* fork: build_edges (DRAM-bound) + prep_v2 run parallel to sgemm1 */
    cudaEventRecord(ev_fork, 0);
    cudaStreamWaitEvent(s_side, ev_fork, 0);
    cudaStreamWaitEvent(s_side2, ev_fork, 0);
    build_edges<<<N_NODES, 256, 0, s_side>>>(adj);
    cudaEventRecord(ev_join, s_side);
    prep_v2<<<32, 256, 0, s_side2>>>(W_out, a_out);
    cudaEventRecord(ev_join2, s_side2);

    {
        dim3 grid(NHEADS, N_NODES / 64);
        sgemm1<<<grid, 256>>>(x, Ws, a_heads);
    }

    /* join before agg1 (needs edge lists + v2 + Wh + f-scores) */
    cudaStreamWaitEvent(0, ev_join, 0);
    cudaStreamWaitEvent(0, ev_join2, 0);
    agg1<<<N_NODES, 256>>>();
    {
        dim3 grid((NCLASS + 63) / 64, N_NODES / 64);
        sgemm2<<<grid, 256>>>(p_hcat, W_out);
    }
    agg2<<<N_NODES, 128>>>(out);
}

// round 12
// speedup vs baseline: 1.0116x; 1.0116x over previous
#include <cuda_runtime.h>
#include <cuda_fp16.h>
#include <math.h>

#define N_NODES 8192
#define NFEAT   256
#define NHID    64
#define NHEADS  4
#define DHID    (NHEADS*NHID)   /* 256 */
#define NCLASS  121
#define LDC2    128             /* padded ld for Whc (halfs) */
#define MAXDEG  512
#define SWPAD   (MAXDEG + 8)
#define LRELU_ALPHA 0.2f

/* ---------------- scratch (static device globals; no allocs) -------------- */
__device__ __half g_Wh_h[N_NODES * DHID];     /* 4 MB layer-1 Wh (fp16, gather-only) */
__device__ float  g_fs4[N_NODES * 4];         /* interleaved per-node f_src (4 heads) */
__device__ float  g_fd4[N_NODES * 4];         /* interleaved per-node f_dst (4 heads) */
__device__ float  g_hcat[N_NODES * DHID];     /* 8 MB layer-1 output (fp32, GEMM2 A) */
__device__ __half g_Whc_h[N_NODES * LDC2];    /* 2 MB layer-2 Wh (fp16, gather-only) */
__device__ float  g_v2s[DHID];
__device__ float  g_v2d[DHID];
__device__ float  g_f2s[N_NODES];
__device__ float  g_f2d[N_NODES];
__device__ int    g_cols[(size_t)N_NODES * MAXDEG];  /* 16 MB edge lists */
__device__ int    g_deg[N_NODES];

/* ---------------- 1. build per-row edge lists (one pass over adj) --------- */
__global__ void build_edges(const float* __restrict__ adj) {
    int row = blockIdx.x;
    int tid = threadIdx.x;
    const float4* a4 = (const float4*)(adj + (size_t)row * N_NODES + tid * 32);

    float4 v[8];
    int cnt = 0;
#pragma unroll
    for (int q = 0; q < 8; q++) {
        v[q] = a4[q];
        cnt += (v[q].x > 0.f) + (v[q].y > 0.f) + (v[q].z > 0.f) + (v[q].w > 0.f);
    }

    __shared__ int s[256];
    s[tid] = cnt;
    __syncthreads();
    for (int off = 1; off < 256; off <<= 1) {
        int t = (tid >= off) ? s[tid - off] : 0;
        __syncthreads();
        s[tid] += t;
        __syncthreads();
    }
    int pos = s[tid] - cnt;            /* exclusive prefix */
    if (tid == 0) {
        int total = s[255];
        g_deg[row] = total < MAXDEG ? total : MAXDEG;
    }

    int* outc = g_cols + (size_t)row * MAXDEG;
#pragma unroll
    for (int q = 0; q < 8; q++) {
        int base = tid * 32 + q * 4;
        if (v[q].x > 0.f) { if (pos < MAXDEG) outc[pos] = base + 0; pos++; }
        if (v[q].y > 0.f) { if (pos < MAXDEG) outc[pos] = base + 1; pos++; }
        if (v[q].z > 0.f) { if (pos < MAXDEG) outc[pos] = base + 2; pos++; }
        if (v[q].w > 0.f) { if (pos < MAXDEG) outc[pos] = base + 3; pos++; }
    }
}

/* ---------------- 2b. v2 = W_out @ a_out halves (warp per row) ------------ */
__global__ void prep_v2(const float* __restrict__ W_out, const float* __restrict__ a_out) {
    int warp = (blockIdx.x << 3) + (threadIdx.x >> 5);   /* 32 blocks * 8 warps = 256 */
    int lane = threadIdx.x & 31;
    const float* wrow = W_out + (size_t)warp * NCLASS;
    float s = 0.f, d = 0.f;
    for (int c = lane; c < NCLASS; c += 32) {
        float w = wrow[c];
        s += w * a_out[c];
        d += w * a_out[NCLASS + c];
    }
#pragma unroll
    for (int o = 16; o > 0; o >>= 1) {
        s += __shfl_xor_sync(0xffffffffu, s, o);
        d += __shfl_xor_sync(0xffffffffu, d, o);
    }
    if (lane == 0) { g_v2s[warp] = s; g_v2d[warp] = d; }
}

/* ---------------- 3. SGEMM1: Wh = x @ Ws[h], fused f-scores, fp16 out ----- */
/* BM=64, BN=64 (=one head, B read directly from Ws), BK=16, 256 thr, 4x4.  */
__global__ void sgemm1(const float* __restrict__ A, const float* __restrict__ Ws,
                       const float* __restrict__ a_heads) {
    __shared__ float As[16][64];
    __shared__ float Bs[16][64];
    __shared__ float s_as[64], s_ad[64];
    int tid = threadIdx.x;
    int tx = tid & 15, ty = tid >> 4;
    int h = blockIdx.x;                 /* head = column tile */
    int row0 = blockIdx.y * 64;
    const int K = NFEAT;
    const float* B = Ws + (size_t)h * NFEAT * NHID;   /* [256,64] contiguous */

    if (tid < 64)       s_as[tid]      = a_heads[h * 128 + tid];
    else if (tid < 128) s_ad[tid - 64] = a_heads[h * 128 + tid];

    float acc[4][4];
#pragma unroll
    for (int i = 0; i < 4; i++)
#pragma unroll
        for (int j = 0; j < 4; j++) acc[i][j] = 0.f;

    int ar = tid & 63,  ac = (tid >> 6) * 4;
    int br = tid >> 4;
    int bc = (tid & 15) * 4;

    float4 a_reg = *(const float4*)(A + (size_t)(row0 + ar) * K + ac);
    float4 b_reg = *(const float4*)(B + (size_t)br * NHID + bc);
    __syncthreads();   /* covers s_as/s_ad */

    for (int k0 = 0; k0 < K; k0 += 16) {
        As[ac + 0][ar] = a_reg.x; As[ac + 1][ar] = a_reg.y;
        As[ac + 2][ar] = a_reg.z; As[ac + 3][ar] = a_reg.w;
        *(float4*)&Bs[br][bc] = b_reg;
        __syncthreads();

        if (k0 + 16 < K) {
            a_reg = *(const float4*)(A + (size_t)(row0 + ar) * K + (k0 + 16) + ac);
            b_reg = *(const float4*)(B + (size_t)(k0 + 16 + br) * NHID + bc);
        }

#pragma unroll
        for (int kk = 0; kk < 16; kk++) {
            float4 ra = *(const float4*)&As[kk][ty * 4];
            float4 rb = *(const float4*)&Bs[kk][tx * 4];
            float rav[4] = {ra.x, ra.y, ra.z, ra.w};
#pragma unroll
            for (int i = 0; i < 4; i++) {
                acc[i][0] += rav[i] * rb.x;
                acc[i][1] += rav[i] * rb.y;
                acc[i][2] += rav[i] * rb.z;
                acc[i][3] += rav[i] * rb.w;
            }
        }
        __syncthreads();
    }

    /* store C (fp16) + fused per-head f-scores -> interleaved [node][head] */
#pragma unroll
    for (int i = 0; i < 4; i++) {
        int r = row0 + ty * 4 + i;
        __half2* dst = (__half2*)(g_Wh_h + (size_t)r * DHID + h * 64 + tx * 4);
        dst[0] = __floats2half2_rn(acc[i][0], acc[i][1]);
        dst[1] = __floats2half2_rn(acc[i][2], acc[i][3]);
        float ps = 0.f, pd = 0.f;
#pragma unroll
        for (int j = 0; j < 4; j++) {
            int c = tx * 4 + j;
            ps += acc[i][j] * s_as[c];
            pd += acc[i][j] * s_ad[c];
        }
#pragma unroll
        for (int o = 8; o > 0; o >>= 1) {
            ps += __shfl_xor_sync(0xffffffffu, ps, o);
            pd += __shfl_xor_sync(0xffffffffu, pd, o);
        }
        if (tx == 0) {
            g_fs4[r * 4 + h] = ps;
            g_fd4[r * 4 + h] = pd;
        }
    }
}

/* ---------------- 3b. SGEMM2: Whc = hcat @ W_out -> fp16 (ld 128) --------- */
__global__ void sgemm2(const float* __restrict__ A, const float* __restrict__ B) {
    __shared__ float As[16][64];
    __shared__ float Bs[16][64];
    int tid = threadIdx.x;
    int tx = tid & 15, ty = tid >> 4;
    int row0 = blockIdx.y * 64;
    int col0 = blockIdx.x * 64;
    const int K = DHID, N = NCLASS;

    float acc[4][4];
#pragma unroll
    for (int i = 0; i < 4; i++)
#pragma unroll
        for (int j = 0; j < 4; j++) acc[i][j] = 0.f;

    int ar = tid & 63,  ac = (tid >> 6) * 4;
    int br = tid >> 4;
    int bc = (tid & 15) * 4;

    float4 a_reg = *(const float4*)(A + (size_t)(row0 + ar) * K + ac);
    float  b_reg[4];
#pragma unroll
    for (int j = 0; j < 4; j++) {
        int c = col0 + bc + j;
        b_reg[j] = (c < N) ? B[(size_t)br * N + c] : 0.f;
    }

    for (int k0 = 0; k0 < K; k0 += 16) {
        As[ac + 0][ar] = a_reg.x; As[ac + 1][ar] = a_reg.y;
        As[ac + 2][ar] = a_reg.z; As[ac + 3][ar] = a_reg.w;
#pragma unroll
        for (int j = 0; j < 4; j++) Bs[br][bc + j] = b_reg[j];
        __syncthreads();

        if (k0 + 16 < K) {
            a_reg = *(const float4*)(A + (size_t)(row0 + ar) * K + (k0 + 16) + ac);
#pragma unroll
            for (int j = 0; j < 4; j++) {
                int c = col0 + bc + j;
                b_reg[j] = (c < N) ? B[(size_t)(k0 + 16 + br) * N + c] : 0.f;
            }
        }

#pragma unroll
        for (int kk = 0; kk < 16; kk++) {
            float4 ra = *(const float4*)&As[kk][ty * 4];
            float4 rb = *(const float4*)&Bs[kk][tx * 4];
            float rav[4] = {ra.x, ra.y, ra.z, ra.w};
#pragma unroll
            for (int i = 0; i < 4; i++) {
                acc[i][0] += rav[i] * rb.x;
                acc[i][1] += rav[i] * rb.y;
                acc[i][2] += rav[i] * rb.z;
                acc[i][3] += rav[i] * rb.w;
            }
        }
        __syncthreads();
    }
#pragma unroll
    for (int i = 0; i < 4; i++) {
        int r = row0 + ty * 4 + i;
#pragma unroll
        for (int j = 0; j < 4; j++) {
            int c = col0 + tx * 4 + j;
            if (c < LDC2)
                g_Whc_h[(size_t)r * LDC2 + c] = __float2half_rn(c < N ? acc[i][j] : 0.f);
        }
    }
}

/* ---------------- 5. layer-1 softmax-aggregate + ELU + fused f2 ----------- */
/* 256 threads. Softmax: 1 edge/thread for all 4 heads (16B fd4 loads).      */
/* Gather: 32 feat-lanes x 8 features (16B) x 8 edge-chunks.                 */
__global__ void agg1() {
    int row = blockIdx.x, tid = threadIdx.x;
    __shared__ int    s_col[MAXDEG];
    __shared__ float  s_w[NHEADS][SWPAD];
    __shared__ float4 s_r4[8];
    __shared__ float4 s_m4v, s_d4v;
    __shared__ float4 s_red[7][64];

    int deg = g_deg[row];
    for (int k = tid; k < deg; k += 256)
        s_col[k] = g_cols[(size_t)row * MAXDEG + k];
    __syncthreads();

    float4 fsv = *(const float4*)(g_fs4 + row * 4);

    /* pass A: one edge per thread, all 4 heads from one 16B load */
    float m0 = -1e30f, m1 = -1e30f, m2 = -1e30f, m3 = -1e30f;
    for (int k = tid; k < deg; k += 256) {
        float4 fd = *(const float4*)(g_fd4 + s_col[k] * 4);
        float e0 = fsv.x + fd.x; e0 = (e0 > 0.f) ? e0 : LRELU_ALPHA * e0;
        float e1 = fsv.y + fd.y; e1 = (e1 > 0.f) ? e1 : LRELU_ALPHA * e1;
        float e2 = fsv.z + fd.z; e2 = (e2 > 0.f) ? e2 : LRELU_ALPHA * e2;
        float e3 = fsv.w + fd.w; e3 = (e3 > 0.f) ? e3 : LRELU_ALPHA * e3;
        s_w[0][k] = e0; s_w[1][k] = e1; s_w[2][k] = e2; s_w[3][k] = e3;
        m0 = fmaxf(m0, e0); m1 = fmaxf(m1, e1);
        m2 = fmaxf(m2, e2); m3 = fmaxf(m3, e3);
    }
#pragma unroll
    for (int o = 16; o > 0; o >>= 1) {
        m0 = fmaxf(m0, __shfl_xor_sync(0xffffffffu, m0, o));
        m1 = fmaxf(m1, __shfl_xor_sync(0xffffffffu, m1, o));
        m2 = fmaxf(m2, __shfl_xor_sync(0xffffffffu, m2, o));
        m3 = fmaxf(m3, __shfl_xor_sync(0xffffffffu, m3, o));
    }
    int w = tid >> 5;
    if ((tid & 31) == 0) s_r4[w] = make_float4(m0, m1, m2, m3);
    __syncthreads();
    if (tid == 0) {
        float4 t = s_r4[0];
#pragma unroll
        for (int i = 1; i < 8; i++) {
            float4 u = s_r4[i];
            t.x = fmaxf(t.x, u.x); t.y = fmaxf(t.y, u.y);
            t.z = fmaxf(t.z, u.z); t.w = fmaxf(t.w, u.w);
        }
        s_m4v = t;
    }
    __syncthreads();
    float4 mh = s_m4v;

    /* pass B: exp + sums, all 4 heads per edge */
    float l0 = 0.f, l1 = 0.f, l2 = 0.f, l3 = 0.f;
    for (int k = tid; k < deg; k += 256) {
        float w0 = __expf(s_w[0][k] - mh.x); s_w[0][k] = w0; l0 += w0;
        float w1 = __expf(s_w[1][k] - mh.y); s_w[1][k] = w1; l1 += w1;
        float w2 = __expf(s_w[2][k] - mh.z); s_w[2][k] = w2; l2 += w2;
        float w3 = __expf(s_w[3][k] - mh.w); s_w[3][k] = w3; l3 += w3;
    }
#pragma unroll
    for (int o = 16; o > 0; o >>= 1) {
        l0 += __shfl_xor_sync(0xffffffffu, l0, o);
        l1 += __shfl_xor_sync(0xffffffffu, l1, o);
        l2 += __shfl_xor_sync(0xffffffffu, l2, o);
        l3 += __shfl_xor_sync(0xffffffffu, l3, o);
    }
    if ((tid & 31) == 0) s_r4[w] = make_float4(l0, l1, l2, l3);
    __syncthreads();
    if (tid == 0) {
        float4 t = s_r4[0];
#pragma unroll
        for (int i = 1; i < 8; i++) {
            float4 u = s_r4[i];
            t.x += u.x; t.y += u.y; t.z += u.z; t.w += u.w;
        }
        s_d4v = t;
    }
    __syncthreads();
    float4 dv = s_d4v;

    /* pass C gather: lane = 8 features (16B), 8 edge-chunks */
    int lane = tid & 31;
    int chunk = tid >> 5;             /* 0..7 */
    int f8 = lane * 8;
    int hh = lane >> 3;               /* head of these 8 features */
    const float* wrow = s_w[hh];
    float a0 = 0.f, a1 = 0.f, a2 = 0.f, a3 = 0.f;
    float a4 = 0.f, a5 = 0.f, a6 = 0.f, a7 = 0.f;
    for (int k = chunk; k < deg; k += 8) {
        float wv = wrow[k];
        uint4 u = *(const uint4*)(g_Wh_h + (size_t)s_col[k] * DHID + f8);
        float2 p0 = __half22float2(*(__half2*)&u.x);
        float2 p1 = __half22float2(*(__half2*)&u.y);
        float2 p2 = __half22float2(*(__half2*)&u.z);
        float2 p3 = __half22float2(*(__half2*)&u.w);
        a0 += wv * p0.x; a1 += wv * p0.y; a2 += wv * p1.x; a3 += wv * p1.y;
        a4 += wv * p2.x; a5 += wv * p2.y; a6 += wv * p3.x; a7 += wv * p3.y;
    }
    if (chunk > 0) {
        s_red[chunk - 1][lane * 2]     = make_float4(a0, a1, a2, a3);
        s_red[chunk - 1][lane * 2 + 1] = make_float4(a4, a5, a6, a7);
    }
    __syncthreads();
    if (chunk == 0) {                  /* exactly warp 0 */
#pragma unroll
        for (int c = 0; c < 7; c++) {
            float4 t = s_red[c][lane * 2];
            float4 t2 = s_red[c][lane * 2 + 1];
            a0 += t.x; a1 += t.y; a2 += t.z; a3 += t.w;
            a4 += t2.x; a5 += t2.y; a6 += t2.z; a7 += t2.w;
        }
        float dh = (hh == 0) ? dv.x : (hh == 1) ? dv.y : (hh == 2) ? dv.z : dv.w;
        float inv = 1.f / dh;
        a0 *= inv; a1 *= inv; a2 *= inv; a3 *= inv;
        a4 *= inv; a5 *= inv; a6 *= inv; a7 *= inv;
        a0 = (a0 > 0.f) ? a0 : expm1f(a0);
        a1 = (a1 > 0.f) ? a1 : expm1f(a1);
        a2 = (a2 > 0.f) ? a2 : expm1f(a2);
        a3 = (a3 > 0.f) ? a3 : expm1f(a3);
        a4 = (a4 > 0.f) ? a4 : expm1f(a4);
        a5 = (a5 > 0.f) ? a5 : expm1f(a5);
        a6 = (a6 > 0.f) ? a6 : expm1f(a6);
        a7 = (a7 > 0.f) ? a7 : expm1f(a7);
        float* orow = g_hcat + (size_t)row * DHID + f8;
        *(float4*)(orow)     = make_float4(a0, a1, a2, a3);
        *(float4*)(orow + 4) = make_float4(a4, a5, a6, a7);
        /* fused layer-2 f-scores (warp 0 only -> pure shuffle reduce) */
        float ps = a0 * g_v2s[f8]     + a1 * g_v2s[f8 + 1] + a2 * g_v2s[f8 + 2] + a3 * g_v2s[f8 + 3]
                 + a4 * g_v2s[f8 + 4] + a5 * g_v2s[f8 + 5] + a6 * g_v2s[f8 + 6] + a7 * g_v2s[f8 + 7];
        float pd = a0 * g_v2d[f8]     + a1 * g_v2d[f8 + 1] + a2 * g_v2d[f8 + 2] + a3 * g_v2d[f8 + 3]
                 + a4 * g_v2d[f8 + 4] + a5 * g_v2d[f8 + 5] + a6 * g_v2d[f8 + 6] + a7 * g_v2d[f8 + 7];
#pragma unroll
        for (int o = 16; o > 0; o >>= 1) {
            ps += __shfl_xor_sync(0xffffffffu, ps, o);
            pd += __shfl_xor_sync(0xffffffffu, pd, o);
        }
        if (lane == 0) {
            g_f2s[row] = ps;
            g_f2d[row] = pd;
        }
    }
}

/* ---------------- 7. layer-2 softmax-aggregate (no ELU) ------------------- */
/* 128 threads. Gather: 16 feat-lanes x 8 features (16B) x 8 edge-chunks.    */
__global__ void agg2(float* __restrict__ out) {
    int row = blockIdx.x, tid = threadIdx.x;
    __shared__ int    s_col[MAXDEG];
    __shared__ float  s_w[MAXDEG];
    __shared__ float  s_rmax[4], s_rsum[4];
    __shared__ float  s_m, s_den;
    __shared__ float4 s_red[7][32];

    int deg = g_deg[row];
    for (int k = tid; k < deg; k += 128)
        s_col[k] = g_cols[(size_t)row * MAXDEG + k];
    __syncthreads();

    float fsi = g_f2s[row];
    float m = -1e30f;
    for (int k = tid; k < deg; k += 128) {
        float e = fsi + __ldg(g_f2d + s_col[k]);
        e = (e > 0.f) ? e : LRELU_ALPHA * e;
        s_w[k] = e;
        m = fmaxf(m, e);
    }
#pragma unroll
    for (int o = 16; o > 0; o >>= 1) m = fmaxf(m, __shfl_xor_sync(0xffffffffu, m, o));
    int w = tid >> 5;
    if ((tid & 31) == 0) s_rmax[w] = m;
    __syncthreads();
    if (tid == 0) s_m = fmaxf(fmaxf(s_rmax[0], s_rmax[1]), fmaxf(s_rmax[2], s_rmax[3]));
    __syncthreads();
    float mh = s_m;

    float lsum = 0.f;
    for (int k = tid; k < deg; k += 128) {
        float wv = __expf(s_w[k] - mh);
        s_w[k] = wv;
        lsum += wv;
    }
#pragma unroll
    for (int o = 16; o > 0; o >>= 1) lsum += __shfl_xor_sync(0xffffffffu, lsum, o);
    if ((tid & 31) == 0) s_rsum[w] = lsum;
    __syncthreads();
    if (tid == 0) s_den = s_rsum[0] + s_rsum[1] + s_rsum[2] + s_rsum[3];
    __syncthreads();
    float inv = 1.f / s_den;

    int lane = tid & 15;
    int chunk = tid >> 4;             /* 0..7 */
    int f8 = lane * 8;                /* 0..120 */
    float a0 = 0.f, a1 = 0.f, a2 = 0.f, a3 = 0.f;
    float a4 = 0.f, a5 = 0.f, a6 = 0.f, a7 = 0.f;
    for (int k = chunk; k < deg; k += 8) {
        float wv = s_w[k];
        uint4 u = *(const uint4*)(g_Whc_h + (size_t)s_col[k] * LDC2 + f8);
        float2 p0 = __half22float2(*(__half2*)&u.x);
        float2 p1 = __half22float2(*(__half2*)&u.y);
        float2 p2 = __half22float2(*(__half2*)&u.z);
        float2 p3 = __half22float2(*(__half2*)&u.w);
        a0 += wv * p0.x; a1 += wv * p0.y; a2 += wv * p1.x; a3 += wv * p1.y;
        a4 += wv * p2.x; a5 += wv * p2.y; a6 += wv * p3.x; a7 += wv * p3.y;
    }
    if (chunk > 0) {
        s_red[chunk - 1][lane * 2]     = make_float4(a0, a1, a2, a3);
        s_red[chunk - 1][lane * 2 + 1] = make_float4(a4, a5, a6, a7);
    }
    __syncthreads();
    if (chunk == 0) {
#pragma unroll
        for (int c = 0; c < 7; c++) {
            float4 t = s_red[c][lane * 2];
            float4 t2 = s_red[c][lane * 2 + 1];
            a0 += t.x; a1 += t.y; a2 += t.z; a3 += t.w;
            a4 += t2.x; a5 += t2.y; a6 += t2.z; a7 += t2.w;
        }
        a0 *= inv; a1 *= inv; a2 *= inv; a3 *= inv;
        a4 *= inv; a5 *= inv; a6 *= inv; a7 *= inv;
        float* orow = out + (size_t)row * NCLASS;
        float av[8] = {a0, a1, a2, a3, a4, a5, a6, a7};
#pragma unroll
        for (int j = 0; j < 8; j++)
            if (f8 + j < NCLASS) orow[f8 + j] = av[j];
    }
}

/* ---------------- launch ------------------------------------------------- */
extern "C" void kernel_launch(void* const* d_in, const int* in_sizes, int n_in,
                              void* d_out, int out_size) {
    const float* x       = (const float*)d_in[0];   /* [8192,256]  */
    const float* adj     = (const float*)d_in[1];   /* [8192,8192] */
    const float* Ws      = (const float*)d_in[2];   /* [4,256,64]  */
    const float* a_heads = (const float*)d_in[3];   /* [4,128]     */
    const float* W_out   = (const float*)d_in[4];   /* [256,121]   */
    const float* a_out   = (const float*)d_in[5];   /* [242]       */
    float* out = (float*)d_out;                     /* [8192,121]  */

    /* side streams + events created once (host resources only) */
    static cudaStream_t s_side = 0, s_side2 = 0;
    static cudaEvent_t  ev_fork = 0, ev_join = 0, ev_join2 = 0;
    if (s_side == 0) {
        cudaStreamCreateWithFlags(&s_side,  cudaStreamNonBlocking);
        cudaStreamCreateWithFlags(&s_side2, cudaStreamNonBlocking);
        cudaEventCreateWithFlags(&ev_fork,  cudaEventDisableTiming);
        cudaEventCreateWithFlags(&ev_join,  cudaEventDisableTiming);
        cudaEventCreateWithFlags(&ev_join2, cudaEventDisableTiming);
    }

    float* p_hcat; cudaGetSymbolAddress((void**)&p_hcat, g_hcat);

    /* fork: build_edges (DRAM-bound) + prep_v2 run parallel to sgemm1 */
    cudaEventRecord(ev_fork, 0);
    cudaStreamWaitEvent(s_side, ev_fork, 0);
    cudaStreamWaitEvent(s_side2, ev_fork, 0);
    build_edges<<<N_NODES, 256, 0, s_side>>>(adj);
    cudaEventRecord(ev_join, s_side);
    prep_v2<<<32, 256, 0, s_side2>>>(W_out, a_out);
    cudaEventRecord(ev_join2, s_side2);

    {
        dim3 grid(NHEADS, N_NODES / 64);
        sgemm1<<<grid, 256>>>(x, Ws, a_heads);
    }

    /* join before agg1 (needs edge lists + v2 + Wh + f-scores) */
    cudaStreamWaitEvent(0, ev_join, 0);
    cudaStreamWaitEvent(0, ev_join2, 0);
    agg1<<<N_NODES, 256>>>();
    {
        dim3 grid((NCLASS + 63) / 64, N_NODES / 64);
        sgemm2<<<grid, 256>>>(p_hcat, W_out);
    }
    agg2<<<N_NODES, 128>>>(out);
}

// round 14
// speedup vs baseline: 1.0439x; 1.0320x over previous
#include <cuda_runtime.h>
#include <cuda_fp16.h>
#include <math.h>

#define N_NODES 8192
#define NFEAT   256
#define NHID    64
#define NHEADS  4
#define DHID    (NHEADS*NHID)   /* 256 */
#define NCLASS  121
#define LDC2    128             /* padded ld for Whc (halfs) */
#define MAXDEG  512
#define SWPAD   (MAXDEG + 8)
#define LRELU_ALPHA 0.2f

/* ---------------- scratch (static device globals; no allocs) -------------- */
__device__ __half g_Wh_h[N_NODES * DHID];     /* 4 MB layer-1 Wh (fp16, gather-only) */
__device__ float  g_fs4[N_NODES * 4];         /* interleaved per-node f_src (4 heads) */
__device__ float  g_fd4[N_NODES * 4];         /* interleaved per-node f_dst (4 heads) */
__device__ float  g_ew[(size_t)N_NODES * MAXDEG * 4];  /* 64 MB edge logits/weights x4 heads */
__device__ float  g_inv1[N_NODES * 4];        /* per-row per-head 1/sum */
__device__ float  g_hcat[N_NODES * DHID];     /* 8 MB layer-1 output (fp32, GEMM2 A) */
__device__ __half g_Whc_h[N_NODES * LDC2];    /* 2 MB layer-2 Wh (fp16, gather-only) */
__device__ float  g_v2s[DHID];
__device__ float  g_v2d[DHID];
__device__ float  g_f2s[N_NODES];
__device__ float  g_f2d[N_NODES];
__device__ float  g_w2[(size_t)N_NODES * MAXDEG];      /* 16 MB layer-2 edge weights */
__device__ float  g_inv2[N_NODES];
__device__ int    g_cols[(size_t)N_NODES * MAXDEG];    /* 16 MB edge lists */
__device__ int    g_deg[N_NODES];

/* ---------------- 1. build per-row edge lists (one pass over adj) --------- */
__global__ void build_edges(const float* __restrict__ adj) {
    int row = blockIdx.x;
    int tid = threadIdx.x;
    const float4* a4 = (const float4*)(adj + (size_t)row * N_NODES + tid * 32);

    float4 v[8];
    int cnt = 0;
#pragma unroll
    for (int q = 0; q < 8; q++) {
        v[q] = a4[q];
        cnt += (v[q].x > 0.f) + (v[q].y > 0.f) + (v[q].z > 0.f) + (v[q].w > 0.f);
    }

    __shared__ int s[256];
    s[tid] = cnt;
    __syncthreads();
    for (int off = 1; off < 256; off <<= 1) {
        int t = (tid >= off) ? s[tid - off] : 0;
        __syncthreads();
        s[tid] += t;
        __syncthreads();
    }
    int pos = s[tid] - cnt;            /* exclusive prefix */
    if (tid == 0) {
        int total = s[255];
        g_deg[row] = total < MAXDEG ? total : MAXDEG;
    }

    int* outc = g_cols + (size_t)row * MAXDEG;
#pragma unroll
    for (int q = 0; q < 8; q++) {
        int base = tid * 32 + q * 4;
        if (v[q].x > 0.f) { if (pos < MAXDEG) outc[pos] = base + 0; pos++; }
        if (v[q].y > 0.f) { if (pos < MAXDEG) outc[pos] = base + 1; pos++; }
        if (v[q].z > 0.f) { if (pos < MAXDEG) outc[pos] = base + 2; pos++; }
        if (v[q].w > 0.f) { if (pos < MAXDEG) outc[pos] = base + 3; pos++; }
    }
}

/* ---------------- 2b. v2 = W_out @ a_out halves (warp per row) ------------ */
__global__ void prep_v2(const float* __restrict__ W_out, const float* __restrict__ a_out) {
    int warp = (blockIdx.x << 3) + (threadIdx.x >> 5);
    int lane = threadIdx.x & 31;
    const float* wrow = W_out + (size_t)warp * NCLASS;
    float s = 0.f, d = 0.f;
    for (int c = lane; c < NCLASS; c += 32) {
        float w = wrow[c];
        s += w * a_out[c];
        d += w * a_out[NCLASS + c];
    }
#pragma unroll
    for (int o = 16; o > 0; o >>= 1) {
        s += __shfl_xor_sync(0xffffffffu, s, o);
        d += __shfl_xor_sync(0xffffffffu, d, o);
    }
    if (lane == 0) { g_v2s[warp] = s; g_v2d[warp] = d; }
}

/* ---------------- 3. SGEMM1: Wh = x @ Ws[h], fused f-scores, fp16 out ----- */
__global__ void sgemm1(const float* __restrict__ A, const float* __restrict__ Ws,
                       const float* __restrict__ a_heads) {
    __shared__ float As[16][64];
    __shared__ float Bs[16][64];
    __shared__ float s_as[64], s_ad[64];
    int tid = threadIdx.x;
    int tx = tid & 15, ty = tid >> 4;
    int h = blockIdx.x;
    int row0 = blockIdx.y * 64;
    const int K = NFEAT;
    const float* B = Ws + (size_t)h * NFEAT * NHID;

    if (tid < 64)       s_as[tid]      = a_heads[h * 128 + tid];
    else if (tid < 128) s_ad[tid - 64] = a_heads[h * 128 + tid];

    float acc[4][4];
#pragma unroll
    for (int i = 0; i < 4; i++)
#pragma unroll
        for (int j = 0; j < 4; j++) acc[i][j] = 0.f;

    int ar = tid & 63,  ac = (tid >> 6) * 4;
    int br = tid >> 4;
    int bc = (tid & 15) * 4;

    float4 a_reg = *(const float4*)(A + (size_t)(row0 + ar) * K + ac);
    float4 b_reg = *(const float4*)(B + (size_t)br * NHID + bc);
    __syncthreads();

    for (int k0 = 0; k0 < K; k0 += 16) {
        As[ac + 0][ar] = a_reg.x; As[ac + 1][ar] = a_reg.y;
        As[ac + 2][ar] = a_reg.z; As[ac + 3][ar] = a_reg.w;
        *(float4*)&Bs[br][bc] = b_reg;
        __syncthreads();

        if (k0 + 16 < K) {
            a_reg = *(const float4*)(A + (size_t)(row0 + ar) * K + (k0 + 16) + ac);
            b_reg = *(const float4*)(B + (size_t)(k0 + 16 + br) * NHID + bc);
        }

#pragma unroll
        for (int kk = 0; kk < 16; kk++) {
            float4 ra = *(const float4*)&As[kk][ty * 4];
            float4 rb = *(const float4*)&Bs[kk][tx * 4];
            float rav[4] = {ra.x, ra.y, ra.z, ra.w};
#pragma unroll
            for (int i = 0; i < 4; i++) {
                acc[i][0] += rav[i] * rb.x;
                acc[i][1] += rav[i] * rb.y;
                acc[i][2] += rav[i] * rb.z;
                acc[i][3] += rav[i] * rb.w;
            }
        }
        __syncthreads();
    }

#pragma unroll
    for (int i = 0; i < 4; i++) {
        int r = row0 + ty * 4 + i;
        __half2* dst = (__half2*)(g_Wh_h + (size_t)r * DHID + h * 64 + tx * 4);
        dst[0] = __floats2half2_rn(acc[i][0], acc[i][1]);
        dst[1] = __floats2half2_rn(acc[i][2], acc[i][3]);
        float ps = 0.f, pd = 0.f;
#pragma unroll
        for (int j = 0; j < 4; j++) {
            int c = tx * 4 + j;
            ps += acc[i][j] * s_as[c];
            pd += acc[i][j] * s_ad[c];
        }
#pragma unroll
        for (int o = 8; o > 0; o >>= 1) {
            ps += __shfl_xor_sync(0xffffffffu, ps, o);
            pd += __shfl_xor_sync(0xffffffffu, pd, o);
        }
        if (tx == 0) {
            g_fs4[r * 4 + h] = ps;
            g_fd4[r * 4 + h] = pd;
        }
    }
}

/* ---------------- 3b. SGEMM2: Whc = hcat @ W_out -> fp16 (ld 128) --------- */
__global__ void sgemm2(const float* __restrict__ A, const float* __restrict__ B) {
    __shared__ float As[16][64];
    __shared__ float Bs[16][64];
    int tid = threadIdx.x;
    int tx = tid & 15, ty = tid >> 4;
    int row0 = blockIdx.y * 64;
    int col0 = blockIdx.x * 64;
    const int K = DHID, N = NCLASS;

    float acc[4][4];
#pragma unroll
    for (int i = 0; i < 4; i++)
#pragma unroll
        for (int j = 0; j < 4; j++) acc[i][j] = 0.f;

    int ar = tid & 63,  ac = (tid >> 6) * 4;
    int br = tid >> 4;
    int bc = (tid & 15) * 4;

    float4 a_reg = *(const float4*)(A + (size_t)(row0 + ar) * K + ac);
    float  b_reg[4];
#pragma unroll
    for (int j = 0; j < 4; j++) {
        int c = col0 + bc + j;
        b_reg[j] = (c < N) ? B[(size_t)br * N + c] : 0.f;
    }

    for (int k0 = 0; k0 < K; k0 += 16) {
        As[ac + 0][ar] = a_reg.x; As[ac + 1][ar] = a_reg.y;
        As[ac + 2][ar] = a_reg.z; As[ac + 3][ar] = a_reg.w;
#pragma unroll
        for (int j = 0; j < 4; j++) Bs[br][bc + j] = b_reg[j];
        __syncthreads();

        if (k0 + 16 < K) {
            a_reg = *(const float4*)(A + (size_t)(row0 + ar) * K + (k0 + 16) + ac);
#pragma unroll
            for (int j = 0; j < 4; j++) {
                int c = col0 + bc + j;
                b_reg[j] = (c < N) ? B[(size_t)(k0 + 16 + br) * N + c] : 0.f;
            }
        }

#pragma unroll
        for (int kk = 0; kk < 16; kk++) {
            float4 ra = *(const float4*)&As[kk][ty * 4];
            float4 rb = *(const float4*)&Bs[kk][tx * 4];
            float rav[4] = {ra.x, ra.y, ra.z, ra.w};
#pragma unroll
            for (int i = 0; i < 4; i++) {
                acc[i][0] += rav[i] * rb.x;
                acc[i][1] += rav[i] * rb.y;
                acc[i][2] += rav[i] * rb.z;
                acc[i][3] += rav[i] * rb.w;
            }
        }
        __syncthreads();
    }
#pragma unroll
    for (int i = 0; i < 4; i++) {
        int r = row0 + ty * 4 + i;
#pragma unroll
        for (int j = 0; j < 4; j++) {
            int c = col0 + tx * 4 + j;
            if (c < LDC2)
                g_Whc_h[(size_t)r * LDC2 + c] = __float2half_rn(c < N ? acc[i][j] : 0.f);
        }
    }
}

/* ---------------- 4. layer-1 softmax (warp per row, no block syncs) ------- */
__global__ void softmax1() {
    int row = (blockIdx.x << 3) + (threadIdx.x >> 5);
    int lane = threadIdx.x & 31;
    int deg = g_deg[row];
    const int* cols = g_cols + (size_t)row * MAXDEG;
    float* ew = g_ew + (size_t)row * MAXDEG * 4;
    float4 fsv = *(const float4*)(g_fs4 + row * 4);

    /* pass A: logits + max */
    float m0 = -1e30f, m1 = -1e30f, m2 = -1e30f, m3 = -1e30f;
    for (int k = lane; k < deg; k += 32) {
        int c = cols[k];
        float4 fd = *(const float4*)(g_fd4 + c * 4);
        float e0 = fsv.x + fd.x; e0 = (e0 > 0.f) ? e0 : LRELU_ALPHA * e0;
        float e1 = fsv.y + fd.y; e1 = (e1 > 0.f) ? e1 : LRELU_ALPHA * e1;
        float e2 = fsv.z + fd.z; e2 = (e2 > 0.f) ? e2 : LRELU_ALPHA * e2;
        float e3 = fsv.w + fd.w; e3 = (e3 > 0.f) ? e3 : LRELU_ALPHA * e3;
        *(float4*)(ew + (size_t)k * 4) = make_float4(e0, e1, e2, e3);
        m0 = fmaxf(m0, e0); m1 = fmaxf(m1, e1);
        m2 = fmaxf(m2, e2); m3 = fmaxf(m3, e3);
    }
#pragma unroll
    for (int o = 16; o > 0; o >>= 1) {
        m0 = fmaxf(m0, __shfl_xor_sync(0xffffffffu, m0, o));
        m1 = fmaxf(m1, __shfl_xor_sync(0xffffffffu, m1, o));
        m2 = fmaxf(m2, __shfl_xor_sync(0xffffffffu, m2, o));
        m3 = fmaxf(m3, __shfl_xor_sync(0xffffffffu, m3, o));
    }

    /* pass B: exp + sum */
    float l0 = 0.f, l1 = 0.f, l2 = 0.f, l3 = 0.f;
    for (int k = lane; k < deg; k += 32) {
        float4 e = *(const float4*)(ew + (size_t)k * 4);
        float w0 = __expf(e.x - m0); l0 += w0;
        float w1 = __expf(e.y - m1); l1 += w1;
        float w2 = __expf(e.z - m2); l2 += w2;
        float w3 = __expf(e.w - m3); l3 += w3;
        *(float4*)(ew + (size_t)k * 4) = make_float4(w0, w1, w2, w3);
    }
#pragma unroll
    for (int o = 16; o > 0; o >>= 1) {
        l0 += __shfl_xor_sync(0xffffffffu, l0, o);
        l1 += __shfl_xor_sync(0xffffffffu, l1, o);
        l2 += __shfl_xor_sync(0xffffffffu, l2, o);
        l3 += __shfl_xor_sync(0xffffffffu, l3, o);
    }
    if (lane == 0)
        *(float4*)(g_inv1 + row * 4) = make_float4(1.f / l0, 1.f / l1, 1.f / l2, 1.f / l3);
}

/* ---------------- 5. layer-1 gather + ELU + fused f2 ---------------------- */
/* 256 threads: stage cols+w, then 32 feat-lanes x 8 features x 8 chunks.   */
__global__ void gather1() {
    int row = blockIdx.x, tid = threadIdx.x;
    __shared__ int    s_col[MAXDEG];
    __shared__ float  s_w[NHEADS][SWPAD];
    __shared__ float4 s_red[7][64];

    int deg = g_deg[row];
    for (int k = tid; k < deg; k += 256)
        s_col[k] = g_cols[(size_t)row * MAXDEG + k];
    {
        const float* ew = g_ew + (size_t)row * MAXDEG * 4;
        int n4 = deg * 4;
        for (int i = tid; i < n4; i += 256)
            s_w[i & 3][i >> 2] = ew[i];
    }
    __syncthreads();

    int lane = tid & 31;
    int chunk = tid >> 5;             /* 0..7 */
    int f8 = lane * 8;
    int hh = lane >> 3;
    const float* wrow = s_w[hh];
    float a0 = 0.f, a1 = 0.f, a2 = 0.f, a3 = 0.f;
    float a4 = 0.f, a5 = 0.f, a6 = 0.f, a7 = 0.f;
    for (int k = chunk; k < deg; k += 8) {
        float wv = wrow[k];
        uint4 u = *(const uint4*)(g_Wh_h + (size_t)s_col[k] * DHID + f8);
        float2 p0 = __half22float2(*(__half2*)&u.x);
        float2 p1 = __half22float2(*(__half2*)&u.y);
        float2 p2 = __half22float2(*(__half2*)&u.z);
        float2 p3 = __half22float2(*(__half2*)&u.w);
        a0 += wv * p0.x; a1 += wv * p0.y; a2 += wv * p1.x; a3 += wv * p1.y;
        a4 += wv * p2.x; a5 += wv * p2.y; a6 += wv * p3.x; a7 += wv * p3.y;
    }
    if (chunk > 0) {
        s_red[chunk - 1][lane * 2]     = make_float4(a0, a1, a2, a3);
        s_red[chunk - 1][lane * 2 + 1] = make_float4(a4, a5, a6, a7);
    }
    __syncthreads();
    if (chunk == 0) {                  /* exactly warp 0 */
#pragma unroll
        for (int c = 0; c < 7; c++) {
            float4 t = s_red[c][lane * 2];
            float4 t2 = s_red[c][lane * 2 + 1];
            a0 += t.x; a1 += t.y; a2 += t.z; a3 += t.w;
            a4 += t2.x; a5 += t2.y; a6 += t2.z; a7 += t2.w;
        }
        float inv = g_inv1[row * 4 + hh];
        a0 *= inv; a1 *= inv; a2 *= inv; a3 *= inv;
        a4 *= inv; a5 *= inv; a6 *= inv; a7 *= inv;
        a0 = (a0 > 0.f) ? a0 : expm1f(a0);
        a1 = (a1 > 0.f) ? a1 : expm1f(a1);
        a2 = (a2 > 0.f) ? a2 : expm1f(a2);
        a3 = (a3 > 0.f) ? a3 : expm1f(a3);
        a4 = (a4 > 0.f) ? a4 : expm1f(a4);
        a5 = (a5 > 0.f) ? a5 : expm1f(a5);
        a6 = (a6 > 0.f) ? a6 : expm1f(a6);
        a7 = (a7 > 0.f) ? a7 : expm1f(a7);
        float* orow = g_hcat + (size_t)row * DHID + f8;
        *(float4*)(orow)     = make_float4(a0, a1, a2, a3);
        *(float4*)(orow + 4) = make_float4(a4, a5, a6, a7);
        float ps = a0 * g_v2s[f8]     + a1 * g_v2s[f8 + 1] + a2 * g_v2s[f8 + 2] + a3 * g_v2s[f8 + 3]
                 + a4 * g_v2s[f8 + 4] + a5 * g_v2s[f8 + 5] + a6 * g_v2s[f8 + 6] + a7 * g_v2s[f8 + 7];
        float pd = a0 * g_v2d[f8]     + a1 * g_v2d[f8 + 1] + a2 * g_v2d[f8 + 2] + a3 * g_v2d[f8 + 3]
                 + a4 * g_v2d[f8 + 4] + a5 * g_v2d[f8 + 5] + a6 * g_v2d[f8 + 6] + a7 * g_v2d[f8 + 7];
#pragma unroll
        for (int o = 16; o > 0; o >>= 1) {
            ps += __shfl_xor_sync(0xffffffffu, ps, o);
            pd += __shfl_xor_sync(0xffffffffu, pd, o);
        }
        if (lane == 0) {
            g_f2s[row] = ps;
            g_f2d[row] = pd;
        }
    }
}

/* ---------------- 6. layer-2 softmax (warp per row) ----------------------- */
__global__ void softmax2() {
    int row = (blockIdx.x << 3) + (threadIdx.x >> 5);
    int lane = threadIdx.x & 31;
    int deg = g_deg[row];
    const int* cols = g_cols + (size_t)row * MAXDEG;
    float* wp = g_w2 + (size_t)row * MAXDEG;
    float fsi = g_f2s[row];

    float m = -1e30f;
    for (int k = lane; k < deg; k += 32) {
        float e = fsi + g_f2d[cols[k]];
        e = (e > 0.f) ? e : LRELU_ALPHA * e;
        wp[k] = e;
        m = fmaxf(m, e);
    }
#pragma unroll
    for (int o = 16; o > 0; o >>= 1) m = fmaxf(m, __shfl_xor_sync(0xffffffffu, m, o));

    float lsum = 0.f;
    for (int k = lane; k < deg; k += 32) {
        float wv = __expf(wp[k] - m);
        wp[k] = wv;
        lsum += wv;
    }
#pragma unroll
    for (int o = 16; o > 0; o >>= 1) lsum += __shfl_xor_sync(0xffffffffu, lsum, o);
    if (lane == 0) g_inv2[row] = 1.f / lsum;
}

/* ---------------- 7. layer-2 gather ---------------------------------------- */
/* 128 threads: stage cols+w, then 16 feat-lanes x 8 features x 8 chunks.    */
__global__ void gather2(float* __restrict__ out) {
    int row = blockIdx.x, tid = threadIdx.x;
    __shared__ int    s_col[MAXDEG];
    __shared__ float  s_w[MAXDEG];
    __shared__ float4 s_red[7][32];

    int deg = g_deg[row];
    for (int k = tid; k < deg; k += 128) {
        s_col[k] = g_cols[(size_t)row * MAXDEG + k];
        s_w[k]   = g_w2[(size_t)row * MAXDEG + k];
    }
    __syncthreads();

    float inv = g_inv2[row];
    int lane = tid & 15;
    int chunk = tid >> 4;             /* 0..7 */
    int f8 = lane * 8;
    float a0 = 0.f, a1 = 0.f, a2 = 0.f, a3 = 0.f;
    float a4 = 0.f, a5 = 0.f, a6 = 0.f, a7 = 0.f;
    for (int k = chunk; k < deg; k += 8) {
        float wv = s_w[k];
        uint4 u = *(const uint4*)(g_Whc_h + (size_t)s_col[k] * LDC2 + f8);
        float2 p0 = __half22float2(*(__half2*)&u.x);
        float2 p1 = __half22float2(*(__half2*)&u.y);
        float2 p2 = __half22float2(*(__half2*)&u.z);
        float2 p3 = __half22float2(*(__half2*)&u.w);
        a0 += wv * p0.x; a1 += wv * p0.y; a2 += wv * p1.x; a3 += wv * p1.y;
        a4 += wv * p2.x; a5 += wv * p2.y; a6 += wv * p3.x; a7 += wv * p3.y;
    }
    if (chunk > 0) {
        s_red[chunk - 1][lane * 2]     = make_float4(a0, a1, a2, a3);
        s_red[chunk - 1][lane * 2 + 1] = make_float4(a4, a5, a6, a7);
    }
    __syncthreads();
    if (chunk == 0) {
#pragma unroll
        for (int c = 0; c < 7; c++) {
            float4 t = s_red[c][lane * 2];
            float4 t2 = s_red[c][lane * 2 + 1];
            a0 += t.x; a1 += t.y; a2 += t.z; a3 += t.w;
            a4 += t2.x; a5 += t2.y; a6 += t2.z; a7 += t2.w;
        }
        a0 *= inv; a1 *= inv; a2 *= inv; a3 *= inv;
        a4 *= inv; a5 *= inv; a6 *= inv; a7 *= inv;
        float* orow = out + (size_t)row * NCLASS;
        float av[8] = {a0, a1, a2, a3, a4, a5, a6, a7};
#pragma unroll
        for (int j = 0; j < 8; j++)
            if (f8 + j < NCLASS) orow[f8 + j] = av[j];
    }
}

/* ---------------- launch ------------------------------------------------- */
extern "C" void kernel_launch(void* const* d_in, const int* in_sizes, int n_in,
                              void* d_out, int out_size) {
    const float* x       = (const float*)d_in[0];   /* [8192,256]  */
    const float* adj     = (const float*)d_in[1];   /* [8192,8192] */
    const float* Ws      = (const float*)d_in[2];   /* [4,256,64]  */
    const float* a_heads = (const float*)d_in[3];   /* [4,128]     */
    const float* W_out   = (const float*)d_in[4];   /* [256,121]   */
    const float* a_out   = (const float*)d_in[5];   /* [242]       */
    float* out = (float*)d_out;                     /* [8192,121]  */

    /* side streams + events created once (host resources only) */
    static cudaStream_t s_side = 0, s_side2 = 0;
    static cudaEvent_t  ev_fork = 0, ev_join = 0, ev_join2 = 0,
                        ev_fork2 = 0, ev_join3 = 0;
    if (s_side == 0) {
        cudaStreamCreateWithFlags(&s_side,  cudaStreamNonBlocking);
        cudaStreamCreateWithFlags(&s_side2, cudaStreamNonBlocking);
        cudaEventCreateWithFlags(&ev_fork,  cudaEventDisableTiming);
        cudaEventCreateWithFlags(&ev_join,  cudaEventDisableTiming);
        cudaEventCreateWithFlags(&ev_join2, cudaEventDisableTiming);
        cudaEventCreateWithFlags(&ev_fork2, cudaEventDisableTiming);
        cudaEventCreateWithFlags(&ev_join3, cudaEventDisableTiming);
    }

    float* p_hcat; cudaGetSymbolAddress((void**)&p_hcat, g_hcat);

    /* fork: build_edges (DRAM-bound) + prep_v2 run parallel to sgemm1 */
    cudaEventRecord(ev_fork, 0);
    cudaStreamWaitEvent(s_side, ev_fork, 0);
    cudaStreamWaitEvent(s_side2, ev_fork, 0);
    build_edges<<<N_NODES, 256, 0, s_side>>>(adj);
    cudaEventRecord(ev_join, s_side);
    prep_v2<<<32, 256, 0, s_side2>>>(W_out, a_out);
    cudaEventRecord(ev_join2, s_side2);

    {
        dim3 grid(NHEADS, N_NODES / 64);
        sgemm1<<<grid, 256>>>(x, Ws, a_heads);
    }

    /* softmax1 needs cols + f-scores */
    cudaStreamWaitEvent(0, ev_join, 0);
    softmax1<<<N_NODES / 8, 256>>>();

    /* gather1 needs softmax1 + Wh + v2 */
    cudaStreamWaitEvent(0, ev_join2, 0);
    gather1<<<N_NODES, 256>>>();

    /* fork: softmax2 (f2-scores + cols) parallel to sgemm2 (hcat) */
    cudaEventRecord(ev_fork2, 0);
    cudaStreamWaitEvent(s_side, ev_fork2, 0);
    softmax2<<<N_NODES / 8, 256, 0, s_side>>>();
    cudaEventRecord(ev_join3, s_side);

    {
        dim3 grid((NCLASS + 63) / 64, N_NODES / 64);
        sgemm2<<<grid, 256>>>(p_hcat, W_out);
    }

    cudaStreamWaitEvent(0, ev_join3, 0);
    gather2<<<N_NODES, 128>>>(out);
}